// round 1
// baseline (speedup 1.0000x reference)
#include <cuda_runtime.h>
#include <math.h>

#define B_  8
#define S_  2048
#define H_  8
#define DK_ 64
#define HD_ 512   // H_*DK_
#define DM_ 512

// Scratch (static device arrays; allocation APIs are forbidden)
__device__ float g_q[(size_t)H_ * B_ * S_ * DK_];
__device__ float g_k[(size_t)H_ * B_ * S_ * DK_];
__device__ float g_v[(size_t)H_ * B_ * S_ * DK_];
__device__ float g_y[(size_t)B_ * S_ * HD_];

// ---------------------------------------------------------------------------
// Generic tiled fp32 GEMM:  C = (A[M,K] @ Bm[K,N] + bias[N]) * out_scale
// BM=BN=64, BK=16, 256 threads, 4x4 microtile.
// SCATTER=true stores to [H,B,S,DK] layout (projection), else row-major [M,N].
// M is implied by grid.y*64; K,N passed (both multiples of 16/64 here).
// ---------------------------------------------------------------------------
template <bool SCATTER>
__global__ void gemm64(const float* __restrict__ A, const float* __restrict__ Bm,
                       const float* __restrict__ bias, float* __restrict__ C,
                       int K, int N, float out_scale)
{
    __shared__ float As[16][68];   // transposed A tile, padded (stride mult of 4)
    __shared__ float Bs[16][64];

    const int t  = threadIdx.x;
    const int tx = t & 15;
    const int ty = t >> 4;
    const int row0 = blockIdx.y * 64;
    const int col0 = blockIdx.x * 64;

    float acc[4][4] = {};

    const int ar  = t >> 2;
    const int akq = (t & 3) * 4;
    const int br  = t >> 4;
    const int bc  = (t & 15) * 4;

    for (int k0 = 0; k0 < K; k0 += 16) {
        float4 av = *(const float4*)&A[(size_t)(row0 + ar) * K + k0 + akq];
        float4 bv = *(const float4*)&Bm[(size_t)(k0 + br) * N + col0 + bc];
        __syncthreads();
        As[akq + 0][ar] = av.x;
        As[akq + 1][ar] = av.y;
        As[akq + 2][ar] = av.z;
        As[akq + 3][ar] = av.w;
        *(float4*)&Bs[br][bc] = bv;
        __syncthreads();
#pragma unroll
        for (int kk = 0; kk < 16; kk++) {
            float4 a = *(float4*)&As[kk][ty * 4];
            float4 b = *(float4*)&Bs[kk][tx * 4];
            acc[0][0] += a.x * b.x; acc[0][1] += a.x * b.y; acc[0][2] += a.x * b.z; acc[0][3] += a.x * b.w;
            acc[1][0] += a.y * b.x; acc[1][1] += a.y * b.y; acc[1][2] += a.y * b.z; acc[1][3] += a.y * b.w;
            acc[2][0] += a.z * b.x; acc[2][1] += a.z * b.y; acc[2][2] += a.z * b.z; acc[2][3] += a.z * b.w;
            acc[3][0] += a.w * b.x; acc[3][1] += a.w * b.y; acc[3][2] += a.w * b.z; acc[3][3] += a.w * b.w;
        }
    }

#pragma unroll
    for (int ii = 0; ii < 4; ii++) {
        const int row = row0 + ty * 4 + ii;
#pragma unroll
        for (int jj = 0; jj < 4; jj++) {
            const int col = col0 + tx * 4 + jj;
            float v = (acc[ii][jj] + bias[col]) * out_scale;
            if (SCATTER) {
                // row = b*S + s ; col = h*DK + d  ->  [((h*B+b)*S+s)*DK + d]
                const int b = row >> 11;           // /S_
                const int s = row & (S_ - 1);
                const int h = col >> 6;            // /DK_
                const int d = col & (DK_ - 1);
                C[((size_t)(h * B_ + b) * S_ + s) * DK_ + d] = v;
            } else {
                C[(size_t)row * N + col] = v;
            }
        }
    }
}

// ---------------------------------------------------------------------------
// Flash attention, fp32. One CTA = (h, qblock of 64, b). 256 threads, 4x4 micro.
// Q is pre-scaled by 1/8. mask==1.0 -> logit = NEG.
// Output written directly in [B,S,H*DK] layout for the final GEMM.
// ---------------------------------------------------------------------------
#define ATTN_SMEM_FLOATS (64 * 68 * 3 + 64 * 64)

__global__ void attn_kernel(const float* __restrict__ mask, float* __restrict__ Y)
{
    extern __shared__ float sm[];
    float* Qst = sm;                 // [64 dk][68]  (transposed)
    float* Kst = Qst + 64 * 68;      // [64 dk][68]  (transposed)
    float* Ps  = Kst + 64 * 68;      // [64 q][68]
    float* Vs  = Ps  + 64 * 68;      // [64 k][64]

    const int h  = blockIdx.x;
    const int qb = blockIdx.y;
    const int b  = blockIdx.z;
    const int t  = threadIdx.x;
    const int tx = t & 15;
    const int ty = t >> 4;

    const size_t base = (size_t)(h * B_ + b) * S_ * DK_;
    const float* Qg = g_q + base + (size_t)qb * 64 * DK_;
    const float* Kg = g_k + base;
    const float* Vg = g_v + base;

    // load Q tile transposed (dk-major)
#pragma unroll
    for (int p = 0; p < 4; p++) {
        const int r  = (t >> 4) + p * 16;
        const int c4 = (t & 15) * 4;
        float4 v = *(const float4*)&Qg[r * DK_ + c4];
        Qst[(c4 + 0) * 68 + r] = v.x;
        Qst[(c4 + 1) * 68 + r] = v.y;
        Qst[(c4 + 2) * 68 + r] = v.z;
        Qst[(c4 + 3) * 68 + r] = v.w;
    }

    float acc[4][4] = {};
    float mrun[4], lrun[4];
#pragma unroll
    for (int ii = 0; ii < 4; ii++) { mrun[ii] = -INFINITY; lrun[ii] = 0.0f; }

    __syncthreads();

    const float NEGV = -2147483648.0f;  // -2^31 per source

    for (int kb = 0; kb < S_ / 64; kb++) {
        const int k0 = kb * 64;
        // load K tile transposed + V tile row-major
#pragma unroll
        for (int p = 0; p < 4; p++) {
            const int r  = (t >> 4) + p * 16;
            const int c4 = (t & 15) * 4;
            float4 kv = *(const float4*)&Kg[(size_t)(k0 + r) * DK_ + c4];
            Kst[(c4 + 0) * 68 + r] = kv.x;
            Kst[(c4 + 1) * 68 + r] = kv.y;
            Kst[(c4 + 2) * 68 + r] = kv.z;
            Kst[(c4 + 3) * 68 + r] = kv.w;
            float4 vv = *(const float4*)&Vg[(size_t)(k0 + r) * DK_ + c4];
            *(float4*)&Vs[r * 64 + c4] = vv;
        }
        __syncthreads();

        // S = Q @ K^T   (Q pre-scaled)
        float s[4][4] = {};
#pragma unroll 16
        for (int kk = 0; kk < 64; kk++) {
            float4 a  = *(float4*)&Qst[kk * 68 + ty * 4];
            float4 bb = *(float4*)&Kst[kk * 68 + tx * 4];
            s[0][0] += a.x * bb.x; s[0][1] += a.x * bb.y; s[0][2] += a.x * bb.z; s[0][3] += a.x * bb.w;
            s[1][0] += a.y * bb.x; s[1][1] += a.y * bb.y; s[1][2] += a.y * bb.z; s[1][3] += a.y * bb.w;
            s[2][0] += a.z * bb.x; s[2][1] += a.z * bb.y; s[2][2] += a.z * bb.z; s[2][3] += a.z * bb.w;
            s[3][0] += a.w * bb.x; s[3][1] += a.w * bb.y; s[3][2] += a.w * bb.z; s[3][3] += a.w * bb.w;
        }

        // mask + online softmax (row stats replicated across the 16 tx lanes)
#pragma unroll
        for (int ii = 0; ii < 4; ii++) {
            const size_t qg = (size_t)b * S_ + qb * 64 + ty * 4 + ii;
            float4 mv = *(const float4*)&mask[qg * S_ + k0 + tx * 4];
            float e0 = (mv.x == 1.0f) ? NEGV : s[ii][0];
            float e1 = (mv.y == 1.0f) ? NEGV : s[ii][1];
            float e2 = (mv.z == 1.0f) ? NEGV : s[ii][2];
            float e3 = (mv.w == 1.0f) ? NEGV : s[ii][3];

            float mx = fmaxf(fmaxf(e0, e1), fmaxf(e2, e3));
            mx = fmaxf(mx, __shfl_xor_sync(0xffffffffu, mx, 1, 16));
            mx = fmaxf(mx, __shfl_xor_sync(0xffffffffu, mx, 2, 16));
            mx = fmaxf(mx, __shfl_xor_sync(0xffffffffu, mx, 4, 16));
            mx = fmaxf(mx, __shfl_xor_sync(0xffffffffu, mx, 8, 16));

            const float mnew = fmaxf(mrun[ii], mx);
            const float corr = __expf(mrun[ii] - mnew);
            const float p0 = __expf(e0 - mnew);
            const float p1 = __expf(e1 - mnew);
            const float p2 = __expf(e2 - mnew);
            const float p3 = __expf(e3 - mnew);

            float rs = (p0 + p1) + (p2 + p3);
            rs += __shfl_xor_sync(0xffffffffu, rs, 1, 16);
            rs += __shfl_xor_sync(0xffffffffu, rs, 2, 16);
            rs += __shfl_xor_sync(0xffffffffu, rs, 4, 16);
            rs += __shfl_xor_sync(0xffffffffu, rs, 8, 16);

            lrun[ii] = lrun[ii] * corr + rs;
            mrun[ii] = mnew;
            acc[ii][0] *= corr; acc[ii][1] *= corr; acc[ii][2] *= corr; acc[ii][3] *= corr;

            *(float4*)&Ps[(ty * 4 + ii) * 68 + tx * 4] = make_float4(p0, p1, p2, p3);
        }
        __syncthreads();

        // O += P @ V
#pragma unroll 16
        for (int j = 0; j < 64; j++) {
            float4 bv = *(float4*)&Vs[j * 64 + tx * 4];
            float a0 = Ps[(ty * 4 + 0) * 68 + j];
            float a1 = Ps[(ty * 4 + 1) * 68 + j];
            float a2 = Ps[(ty * 4 + 2) * 68 + j];
            float a3 = Ps[(ty * 4 + 3) * 68 + j];
            acc[0][0] += a0 * bv.x; acc[0][1] += a0 * bv.y; acc[0][2] += a0 * bv.z; acc[0][3] += a0 * bv.w;
            acc[1][0] += a1 * bv.x; acc[1][1] += a1 * bv.y; acc[1][2] += a1 * bv.z; acc[1][3] += a1 * bv.w;
            acc[2][0] += a2 * bv.x; acc[2][1] += a2 * bv.y; acc[2][2] += a2 * bv.z; acc[2][3] += a2 * bv.w;
            acc[3][0] += a3 * bv.x; acc[3][1] += a3 * bv.y; acc[3][2] += a3 * bv.z; acc[3][3] += a3 * bv.w;
        }
        __syncthreads();
    }

    // normalize + store into [B,S,H*DK]
#pragma unroll
    for (int ii = 0; ii < 4; ii++) {
        const float rl = 1.0f / lrun[ii];
        const size_t row = (size_t)b * S_ + qb * 64 + ty * 4 + ii;
        float4 o = make_float4(acc[ii][0] * rl, acc[ii][1] * rl,
                               acc[ii][2] * rl, acc[ii][3] * rl);
        *(float4*)&Y[row * HD_ + h * DK_ + tx * 4] = o;
    }
}

// ---------------------------------------------------------------------------
extern "C" void kernel_launch(void* const* d_in, const int* in_sizes, int n_in,
                              void* d_out, int out_size)
{
    const float* q    = (const float*)d_in[0];
    const float* k    = (const float*)d_in[1];
    const float* v    = (const float*)d_in[2];
    const float* mask = (const float*)d_in[3];
    const float* Wq   = (const float*)d_in[4];
    const float* bq   = (const float*)d_in[5];
    const float* Wo   = (const float*)d_in[6];
    const float* bo   = (const float*)d_in[7];
    float* out = (float*)d_out;

    float *gq, *gk, *gv, *gy;
    cudaGetSymbolAddress((void**)&gq, g_q);
    cudaGetSymbolAddress((void**)&gk, g_k);
    cudaGetSymbolAddress((void**)&gv, g_v);
    cudaGetSymbolAddress((void**)&gy, g_y);

    const int attn_smem = ATTN_SMEM_FLOATS * (int)sizeof(float);
    cudaFuncSetAttribute(attn_kernel, cudaFuncAttributeMaxDynamicSharedMemorySize, attn_smem);

    const int Mrows = B_ * S_;                 // 16384
    dim3 blk(256);

    // projections (note reference bug: Wq/bq for q, k AND v); 1/sqrt(DK) folded into Q
    dim3 gproj(HD_ / 64, Mrows / 64);
    gemm64<true><<<gproj, blk>>>(q, Wq, bq, gq, DK_, HD_, 0.125f);
    gemm64<true><<<gproj, blk>>>(k, Wq, bq, gk, DK_, HD_, 1.0f);
    gemm64<true><<<gproj, blk>>>(v, Wq, bq, gv, DK_, HD_, 1.0f);

    // flash attention: grid.x = heads (fastest) so the 8 heads of one (b,qb)
    // share mask tiles in L2
    dim3 gattn(H_, S_ / 64, B_);
    attn_kernel<<<gattn, blk, attn_smem>>>(mask, gy);

    // output projection
    dim3 gout(DM_ / 64, Mrows / 64);
    gemm64<false><<<gout, blk>>>(gy, Wo, bo, out, HD_, DM_, 1.0f);
}